// round 7
// baseline (speedup 1.0000x reference)
#include <cuda_runtime.h>
#include <cmath>

#define BB 128
#define LL 512
#define HH 512
#define TT 24
#define TAG_START 22
#define TAG_STOP  23

// Scratch: X[b,l,t] = exp(emit[b,l,t]).  6.3 MB (L2-resident).
__device__ float g_X[BB * LL * TT];

// m16n8k8 tf32 mma
#define MMA_TF32(c0,c1,c2,c3,a0,a1,a2,a3,b0,b1) \
  asm("mma.sync.aligned.m16n8k8.row.col.f32.tf32.tf32.f32 " \
      "{%0,%1,%2,%3},{%4,%5,%6,%7},{%8,%9},{%0,%1,%2,%3};" \
      : "+f"(c0),"+f"(c1),"+f"(c2),"+f"(c3) \
      : "r"(a0),"r"(a1),"r"(a2),"r"(a3),"r"(b0),"r"(b1))

__device__ __forceinline__ unsigned f2tf32(float v) {
    unsigned r;
    asm("cvt.rna.tf32.f32 %0, %1;" : "=r"(r) : "f"(v));
    return r;
}

// bf16 round-to-nearest-even pack of a non-negative, non-NaN float
__device__ __forceinline__ unsigned short bf16_pack(float f) {
    const unsigned u = __float_as_uint(f);
    return (unsigned short)((u + 0x7fffu + ((u >> 16) & 1u)) >> 16);
}

// ---------------------------------------------------------------------------
// Kernel 1: emission GEMM + exp via tf32 tensor cores (unchanged from R6 —
// measured ~27us, ~4.7 TB/s effective, near the LTS cap).
// ---------------------------------------------------------------------------
__global__ void __launch_bounds__(256, 4) emit_kernel(
    const float* __restrict__ feat,
    const float* __restrict__ Wm,
    const float* __restrict__ bias)
{
    __shared__ unsigned Wt[HH * TT];  // 48KB: tf32 bits, layout [k][n]

    const int tid = threadIdx.x;

    for (int i = tid; i < HH * TT; i += 256) {
        const int n = i >> 9;
        const int k = i & 511;
        Wt[k * TT + n] = f2tf32(Wm[i]);
    }
    __syncthreads();

    const int warp = tid >> 5;
    const int lane = tid & 31;
    const int g = lane >> 2;
    const int q = lane & 3;

    const long r0 = (long)blockIdx.x * 128 + warp * 16 + g;
    const float* pA  = feat + r0 * HH + q;
    const float* pA8 = pA + 8 * HH;

    float c0[3], c1[3], c2[3], c3[3];
    #pragma unroll
    for (int nt = 0; nt < 3; ++nt) { c0[nt]=0.f; c1[nt]=0.f; c2[nt]=0.f; c3[nt]=0.f; }

    float f0 = pA[0], f1 = pA8[0], f2 = pA[4], f3 = pA8[4];

    #pragma unroll 4
    for (int k0 = 0; k0 < HH; k0 += 8) {
        const int kn = (k0 + 8 < HH) ? (k0 + 8) : (HH - 8);
        const float n0 = pA [kn];
        const float n1 = pA8[kn];
        const float n2 = pA [kn + 4];
        const float n3 = pA8[kn + 4];

        const unsigned a0 = f2tf32(f0);
        const unsigned a1 = f2tf32(f1);
        const unsigned a2 = f2tf32(f2);
        const unsigned a3 = f2tf32(f3);

        const unsigned* wb0 = Wt + (k0 + q) * TT + g;
        const unsigned* wb1 = wb0 + 4 * TT;
        #pragma unroll
        for (int nt = 0; nt < 3; ++nt) {
            const unsigned b0 = wb0[nt * 8];
            const unsigned b1 = wb1[nt * 8];
            MMA_TF32(c0[nt], c1[nt], c2[nt], c3[nt], a0, a1, a2, a3, b0, b1);
        }

        f0 = n0; f1 = n1; f2 = n2; f3 = n3;
    }

    #pragma unroll
    for (int nt = 0; nt < 3; ++nt) {
        const int col = nt * 8 + 2 * q;
        const float bv0 = __ldg(bias + col);
        const float bv1 = __ldg(bias + col + 1);
        float2 lo = make_float2(__expf(c0[nt] + bv0), __expf(c1[nt] + bv1));
        float2 hi = make_float2(__expf(c2[nt] + bv0), __expf(c3[nt] + bv1));
        *reinterpret_cast<float2*>(g_X + r0 * TT + col)       = lo;
        *reinterpret_cast<float2*>(g_X + (r0 + 8) * TT + col) = hi;
    }
}

// ---------------------------------------------------------------------------
// Kernel 2: linear-domain CRF scan — minimal serial chain per step:
//   STS.U16(bf16 w) -> syncwarp -> 3x broadcast LDS.128 -> 24 FFMA -> FMUL
// NO per-step renormalization. Renorm runs once per 8 steps, unconditionally:
// power-of-2 rescale + Mexp preserves w*2^Mexp EXACTLY (no rounding), so it
// is also a no-op on frozen (t >= len) chains. Overflow-safe: after renorm
// max(w) < 2^1 and per-step growth <= ~2^13.2, so 8 steps <= 2^107 < 2^127.
// bf16 has fp32's exponent range, so the unnormalized exchange is safe.
// ---------------------------------------------------------------------------
__global__ __launch_bounds__(32) void scan_kernel(
    const float* __restrict__ trans,
    const int*   __restrict__ lengths,
    float*       __restrict__ out)
{
    __shared__ __align__(16) unsigned short wbuf[2][32];

    const int lane = threadIdx.x;
    const int b = blockIdx.x;

    // E row for this lane; lanes >= 24 hold zeros.
    float E[TT];
    #pragma unroll
    for (int k = 0; k < TT; ++k)
        E[k] = (lane < TT) ? __expf(trans[lane * TT + k]) : 0.f;
    const float TE = (lane < TT) ? __expf(trans[TAG_STOP * TT + lane]) : 0.f;

    const int len = lengths[b];                 // 1..512, warp-uniform
    const int lanec = (lane < TT) ? lane : (TT - 1);
    const float* Xb = g_X + (size_t)b * LL * TT;
    const bool lv = (lane < TT);

    float w = (lane == TAG_START) ? 1.f : 0.f;  // fp32 linear-domain state
    unsigned short hs = bf16_pack(w);           // bf16 exchange image of w
    int Mexp = 0;

    // 8-deep emission prefetch ring
    float xq[8];
    #pragma unroll
    for (int u = 0; u < 8; ++u)
        xq[u] = lv ? Xb[u * TT + lane] : 0.f;

    for (int t0 = 0; t0 < LL; t0 += 8) {
        #pragma unroll
        for (int u = 0; u < 8; ++u) {
            const int t = t0 + u;
            const bool act = (t < len);         // warp-uniform
            const int p = u & 1;

            wbuf[p][lane] = hs;                 // STS.U16 — start of exchange

            __syncwarp();

            // read all 24 exchanged bf16 values (3 broadcast LDS.128)
            const uint4 v0 = *reinterpret_cast<const uint4*>(&wbuf[p][0]);
            const uint4 v1 = *reinterpret_cast<const uint4*>(&wbuf[p][8]);
            const uint4 v2 = *reinterpret_cast<const uint4*>(&wbuf[p][16]);

            // branch-free prefetch for step t+8, issued after the LDS reads
            const int tn = (t + 8 < LL) ? (t + 8) : (LL - 1);
            const float xl = Xb[tn * TT + lanec];

            unsigned pr[6] = { v0.x, v0.y, v0.z, v0.w, v1.x, v1.y };
            unsigned qr[6] = { v1.z, v1.w, v2.x, v2.y, v2.z, v2.w };

            // dot in fp32: s_j = sum_k E[j][k] * w_k  (bf16->f32 is a shift)
            float a0 = 0.f, a1 = 0.f, a2 = 0.f, a3 = 0.f;
            #pragma unroll
            for (int i = 0; i < 6; ++i) {
                const float wlo = __uint_as_float(pr[i] << 16);
                const float whi = __uint_as_float(pr[i] & 0xffff0000u);
                a0 = fmaf(E[2 * i + 0],  wlo, a0);
                a1 = fmaf(E[2 * i + 1],  whi, a1);
                const float ylo = __uint_as_float(qr[i] << 16);
                const float yhi = __uint_as_float(qr[i] & 0xffff0000u);
                a2 = fmaf(E[12 + 2 * i], ylo, a2);
                a3 = fmaf(E[13 + 2 * i], yhi, a3);
            }
            const float s = (a0 + a1) + (a2 + a3);
            const float wn = xq[u] * s;         // zero for lanes >= 24

            const unsigned short hn = bf16_pack(wn);  // parallel with SELs

            w     = act ? wn : w;               // freeze (SEL)
            hs    = act ? hn : hs;              // freeze (SEL)
            xq[u] = lv ? xl : 0.f;              // rotate prefetch (SEL)

            // unconditional renorm once per 8 steps (exact power-of-2;
            // preserves w * 2^Mexp on active AND frozen chains)
            if (u == 7) {
                const unsigned mb =
                    __reduce_max_sync(0xffffffffu, __float_as_uint(w));
                const int e  = (int)(mb >> 23);
                const int en = (e == 0) ? 127 : e;
                const float nsc =
                    __uint_as_float((unsigned)(254 - en) << 23); // 2^-(en-127)
                w *= nsc;
                Mexp += (en - 127);
                hs = bf16_pack(w);              // keep exchange image in sync
            }
        }
        if (t0 + 8 >= len) break;
    }

    // alpha = log( sum_k w_k * TE_k ) + Mexp*ln2
    float term = w * TE;
    #pragma unroll
    for (int o = 16; o > 0; o >>= 1)
        term += __shfl_xor_sync(0xffffffffu, term, o);

    if (lane == 0)
        out[b] = __logf(term) + (float)Mexp * 0.69314718055994531f;
}

extern "C" void kernel_launch(void* const* d_in, const int* in_sizes, int n_in,
                              void* d_out, int out_size)
{
    const float* feat   = (const float*)d_in[0];  // [128,512,512]
    const float* Wm     = (const float*)d_in[1];  // [24,512]
    const float* bias   = (const float*)d_in[2];  // [24]
    const float* trans  = (const float*)d_in[3];  // [24,24]
    const int*   lens   = (const int*)d_in[4];    // [128]
    float* out = (float*)d_out;                   // [128]

    emit_kernel<<<512, 256>>>(feat, Wm, bias);
    scan_kernel<<<128, 32>>>(trans, lens, out);
}

// round 8
// speedup vs baseline: 1.1747x; 1.1747x over previous
#include <cuda_runtime.h>
#include <cmath>

#define BB 128
#define LL 512
#define HH 512
#define TT 24
#define TAG_START 22
#define TAG_STOP  23

// Scratch: X[b,l,t] = exp(emit[b,l,t]).  6.3 MB (L2-resident).
__device__ float g_X[BB * LL * TT];

// m16n8k8 tf32 mma
#define MMA_TF32(c0,c1,c2,c3,a0,a1,a2,a3,b0,b1) \
  asm("mma.sync.aligned.m16n8k8.row.col.f32.tf32.tf32.f32 " \
      "{%0,%1,%2,%3},{%4,%5,%6,%7},{%8,%9},{%0,%1,%2,%3};" \
      : "+f"(c0),"+f"(c1),"+f"(c2),"+f"(c3) \
      : "r"(a0),"r"(a1),"r"(a2),"r"(a3),"r"(b0),"r"(b1))

__device__ __forceinline__ unsigned f2tf32(float v) {
    unsigned r;
    asm("cvt.rna.tf32.f32 %0, %1;" : "=r"(r) : "f"(v));
    return r;
}

// bf16 round-to-nearest-even pack of a non-negative, non-NaN float
__device__ __forceinline__ unsigned short bf16_pack(float f) {
    const unsigned u = __float_as_uint(f);
    return (unsigned short)((u + 0x7fffu + ((u >> 16) & 1u)) >> 16);
}

// ---------------------------------------------------------------------------
// Kernel 1: emission GEMM + exp via tf32 tensor cores (unchanged; ~27us).
// ---------------------------------------------------------------------------
__global__ void __launch_bounds__(256, 4) emit_kernel(
    const float* __restrict__ feat,
    const float* __restrict__ Wm,
    const float* __restrict__ bias)
{
    __shared__ unsigned Wt[HH * TT];

    const int tid = threadIdx.x;

    for (int i = tid; i < HH * TT; i += 256) {
        const int n = i >> 9;
        const int k = i & 511;
        Wt[k * TT + n] = f2tf32(Wm[i]);
    }
    __syncthreads();

    const int warp = tid >> 5;
    const int lane = tid & 31;
    const int g = lane >> 2;
    const int q = lane & 3;

    const long r0 = (long)blockIdx.x * 128 + warp * 16 + g;
    const float* pA  = feat + r0 * HH + q;
    const float* pA8 = pA + 8 * HH;

    float c0[3], c1[3], c2[3], c3[3];
    #pragma unroll
    for (int nt = 0; nt < 3; ++nt) { c0[nt]=0.f; c1[nt]=0.f; c2[nt]=0.f; c3[nt]=0.f; }

    float f0 = pA[0], f1 = pA8[0], f2 = pA[4], f3 = pA8[4];

    #pragma unroll 4
    for (int k0 = 0; k0 < HH; k0 += 8) {
        const int kn = (k0 + 8 < HH) ? (k0 + 8) : (HH - 8);
        const float n0 = pA [kn];
        const float n1 = pA8[kn];
        const float n2 = pA [kn + 4];
        const float n3 = pA8[kn + 4];

        const unsigned a0 = f2tf32(f0);
        const unsigned a1 = f2tf32(f1);
        const unsigned a2 = f2tf32(f2);
        const unsigned a3 = f2tf32(f3);

        const unsigned* wb0 = Wt + (k0 + q) * TT + g;
        const unsigned* wb1 = wb0 + 4 * TT;
        #pragma unroll
        for (int nt = 0; nt < 3; ++nt) {
            const unsigned b0 = wb0[nt * 8];
            const unsigned b1 = wb1[nt * 8];
            MMA_TF32(c0[nt], c1[nt], c2[nt], c3[nt], a0, a1, a2, a3, b0, b1);
        }

        f0 = n0; f1 = n1; f2 = n2; f3 = n3;
    }

    #pragma unroll
    for (int nt = 0; nt < 3; ++nt) {
        const int col = nt * 8 + 2 * q;
        const float bv0 = __ldg(bias + col);
        const float bv1 = __ldg(bias + col + 1);
        float2 lo = make_float2(__expf(c0[nt] + bv0), __expf(c1[nt] + bv1));
        float2 hi = make_float2(__expf(c2[nt] + bv0), __expf(c3[nt] + bv1));
        *reinterpret_cast<float2*>(g_X + r0 * TT + col)       = lo;
        *reinterpret_cast<float2*>(g_X + (r0 + 8) * TT + col) = hi;
    }
}

// ---------------------------------------------------------------------------
// Kernel 2: meet-in-the-middle CRF scan.  One block (2 warps) per batch b:
//   warp 0 (forward):  v_f = M_{mid-1}...M_0 v0,        M_t = diag(x_t) E
//   warp 1 (backward): y   = M_mid^T...M_{len-1}^T u,   u = exp(trans[STOP,:])
//   alpha = ln( v_f . y ) + (Mexp_f + Mexp_b) ln2,      mid = len/2
// Each chain is <= 256 serial steps; both run concurrently in one block.
// Forward step:  w' = x_t ⊙ (E w)        (emission applied after the dot)
// Backward step: y' = E^T (x_t ⊙ y)      (emission applied before exchange)
// Exchange: bf16 via smem (STS.U16 -> syncwarp -> 3 broadcast LDS.128).
// Exact power-of-2 renorm every 8 steps (safe on frozen chains).
// ---------------------------------------------------------------------------
__global__ __launch_bounds__(64) void scan_kernel(
    const float* __restrict__ trans,
    const int*   __restrict__ lengths,
    float*       __restrict__ out)
{
    __shared__ __align__(16) unsigned short wbuf[2][2][32];
    __shared__ float vres[32];
    __shared__ int   mexp_b_sh;

    const int lane = threadIdx.x & 31;
    const int warp = threadIdx.x >> 5;       // 0 = forward, 1 = backward
    const int b = blockIdx.x;
    const bool fwd = (warp == 0);

    // forward: E[j][k] = exp(trans[j,k]); backward: ET[j][k] = exp(trans[k,j])
    float E[TT];
    #pragma unroll
    for (int k = 0; k < TT; ++k) {
        const int idx = fwd ? (lane * TT + k) : (k * TT + lane);
        E[k] = (lane < TT) ? __expf(trans[idx]) : 0.f;
    }

    const int len = lengths[b];               // 1..512, uniform per block
    const int mid = len >> 1;
    const int steps = fwd ? mid : (len - mid);  // <= 256

    const int lanec = (lane < TT) ? lane : (TT - 1);
    const float* Xb = g_X + (size_t)b * LL * TT;
    const bool lv = (lane < TT);

    float w;
    if (fwd) w = (lane == TAG_START) ? 1.f : 0.f;
    else     w = (lane < TT) ? __expf(trans[TAG_STOP * TT + lane]) : 0.f;
    int Mexp = 0;

    // 8-deep emission prefetch ring; step i uses t = i (fwd) / len-1-i (bwd)
    float xq[8];
    #pragma unroll
    for (int u = 0; u < 8; ++u) {
        int t = fwd ? u : (len - 1 - u);
        t = (t < 0) ? 0 : t;
        xq[u] = lv ? Xb[t * TT + lane] : 0.f;
    }

    unsigned short hs = bf16_pack(fwd ? w : (xq[0] * w));  // first exchange image

    for (int i0 = 0; i0 < LL / 2; i0 += 8) {
        #pragma unroll
        for (int u = 0; u < 8; ++u) {
            const int i = i0 + u;
            const bool act = (i < steps);     // warp-uniform
            const int p = u & 1;

            wbuf[warp][p][lane] = hs;         // start of exchange

            __syncwarp();

            const uint4 v0 = *reinterpret_cast<const uint4*>(&wbuf[warp][p][0]);
            const uint4 v1 = *reinterpret_cast<const uint4*>(&wbuf[warp][p][8]);
            const uint4 v2 = *reinterpret_cast<const uint4*>(&wbuf[warp][p][16]);

            const float xthis = xq[u];        // emission for THIS step (fwd use)

            // branch-free prefetch for step i+8 (clamped, always in-bounds)
            {
                int t = fwd ? (i + 8) : (len - 9 - i);
                t = (t < 0) ? 0 : t;
                const float xl = Xb[t * TT + lanec];
                xq[u] = lv ? xl : 0.f;
            }

            unsigned pr[6] = { v0.x, v0.y, v0.z, v0.w, v1.x, v1.y };
            unsigned qr[6] = { v1.z, v1.w, v2.x, v2.y, v2.z, v2.w };

            float a0 = 0.f, a1 = 0.f, a2 = 0.f, a3 = 0.f;
            #pragma unroll
            for (int ii = 0; ii < 6; ++ii) {
                const float wlo = __uint_as_float(pr[ii] << 16);
                const float whi = __uint_as_float(pr[ii] & 0xffff0000u);
                a0 = fmaf(E[2 * ii + 0],  wlo, a0);
                a1 = fmaf(E[2 * ii + 1],  whi, a1);
                const float ylo = __uint_as_float(qr[ii] << 16);
                const float yhi = __uint_as_float(qr[ii] & 0xffff0000u);
                a2 = fmaf(E[12 + 2 * ii], ylo, a2);
                a3 = fmaf(E[13 + 2 * ii], yhi, a3);
            }
            const float s = (a0 + a1) + (a2 + a3);

            // forward: w' = x_t * (E w);  backward: y' = E^T z (z already had x)
            const float wn = fwd ? (xthis * s) : s;

            w = act ? wn : w;                 // freeze (SEL)

            // next exchange image: fwd -> w ; bwd -> x_{t+1} * y
            const float nx = fwd ? w : (xq[(u + 1) & 7] * w);
            hs = bf16_pack(nx);

            // exact renorm every 8 steps (power-of-2; frozen-safe)
            if (u == 7) {
                const unsigned mb =
                    __reduce_max_sync(0xffffffffu, __float_as_uint(w));
                const int e  = (int)(mb >> 23);
                const int en = (e == 0) ? 127 : e;
                const float nsc =
                    __uint_as_float((unsigned)(254 - en) << 23);
                w *= nsc;
                Mexp += (en - 127);
                hs = bf16_pack(fwd ? w : (xq[0] * w));
            }
        }
        if (i0 + 8 >= steps) break;
    }

    if (warp == 1) {
        vres[lane] = w;
        if (lane == 0) mexp_b_sh = Mexp;
    }
    __syncthreads();

    if (warp == 0) {
        float term = w * vres[lane];
        #pragma unroll
        for (int o = 16; o > 0; o >>= 1)
            term += __shfl_xor_sync(0xffffffffu, term, o);
        if (lane == 0)
            out[b] = __logf(term) +
                     (float)(Mexp + mexp_b_sh) * 0.69314718055994531f;
    }
}

extern "C" void kernel_launch(void* const* d_in, const int* in_sizes, int n_in,
                              void* d_out, int out_size)
{
    const float* feat   = (const float*)d_in[0];  // [128,512,512]
    const float* Wm     = (const float*)d_in[1];  // [24,512]
    const float* bias   = (const float*)d_in[2];  // [24]
    const float* trans  = (const float*)d_in[3];  // [24,24]
    const int*   lens   = (const int*)d_in[4];    // [128]
    float* out = (float*)d_out;                   // [128]

    emit_kernel<<<512, 256>>>(feat, Wm, bias);
    scan_kernel<<<128, 64>>>(trans, lens, out);
}

// round 9
// speedup vs baseline: 1.3175x; 1.1216x over previous
#include <cuda_runtime.h>
#include <cmath>

#define BB 128
#define LL 512
#define HH 512
#define TT 24
#define TAG_START 22
#define TAG_STOP  23
#define SEG 16
#define SS  32            // steps per segment = LL/SEG

// Scratch (device globals; no allocations).
__device__ float g_X[BB * LL * TT];          // exp(emissions)  6.3 MB
__device__ float g_P[BB * SEG * 576];        // segment transport matrices 4.7 MB
__device__ int   g_M[BB * SEG];              // segment exponent offsets

// m16n8k8 tf32 mma
#define MMA_TF32(c0,c1,c2,c3,a0,a1,a2,a3,b0,b1) \
  asm("mma.sync.aligned.m16n8k8.row.col.f32.tf32.tf32.f32 " \
      "{%0,%1,%2,%3},{%4,%5,%6,%7},{%8,%9},{%0,%1,%2,%3};" \
      : "+f"(c0),"+f"(c1),"+f"(c2),"+f"(c3) \
      : "r"(a0),"r"(a1),"r"(a2),"r"(a3),"r"(b0),"r"(b1))

__device__ __forceinline__ unsigned f2tf32(float v) {
    unsigned r;
    asm("cvt.rna.tf32.f32 %0, %1;" : "=r"(r) : "f"(v));
    return r;
}

// ---------------------------------------------------------------------------
// Kernel 1: emission GEMM + exp via tf32 tensor cores (unchanged; ~30us).
// ---------------------------------------------------------------------------
__global__ void __launch_bounds__(256, 4) emit_kernel(
    const float* __restrict__ feat,
    const float* __restrict__ Wm,
    const float* __restrict__ bias)
{
    __shared__ unsigned Wt[HH * TT];

    const int tid = threadIdx.x;

    for (int i = tid; i < HH * TT; i += 256) {
        const int n = i >> 9;
        const int k = i & 511;
        Wt[k * TT + n] = f2tf32(Wm[i]);
    }
    __syncthreads();

    const int warp = tid >> 5;
    const int lane = tid & 31;
    const int g = lane >> 2;
    const int q = lane & 3;

    const long r0 = (long)blockIdx.x * 128 + warp * 16 + g;
    const float* pA  = feat + r0 * HH + q;
    const float* pA8 = pA + 8 * HH;

    float c0[3], c1[3], c2[3], c3[3];
    #pragma unroll
    for (int nt = 0; nt < 3; ++nt) { c0[nt]=0.f; c1[nt]=0.f; c2[nt]=0.f; c3[nt]=0.f; }

    float f0 = pA[0], f1 = pA8[0], f2 = pA[4], f3 = pA8[4];

    #pragma unroll 4
    for (int k0 = 0; k0 < HH; k0 += 8) {
        const int kn = (k0 + 8 < HH) ? (k0 + 8) : (HH - 8);
        const float n0 = pA [kn];
        const float n1 = pA8[kn];
        const float n2 = pA [kn + 4];
        const float n3 = pA8[kn + 4];

        const unsigned a0 = f2tf32(f0);
        const unsigned a1 = f2tf32(f1);
        const unsigned a2 = f2tf32(f2);
        const unsigned a3 = f2tf32(f3);

        const unsigned* wb0 = Wt + (k0 + q) * TT + g;
        const unsigned* wb1 = wb0 + 4 * TT;
        #pragma unroll
        for (int nt = 0; nt < 3; ++nt) {
            const unsigned b0 = wb0[nt * 8];
            const unsigned b1 = wb1[nt * 8];
            MMA_TF32(c0[nt], c1[nt], c2[nt], c3[nt], a0, a1, a2, a3, b0, b1);
        }

        f0 = n0; f1 = n1; f2 = n2; f3 = n3;
    }

    #pragma unroll
    for (int nt = 0; nt < 3; ++nt) {
        const int col = nt * 8 + 2 * q;
        const float bv0 = __ldg(bias + col);
        const float bv1 = __ldg(bias + col + 1);
        float2 lo = make_float2(__expf(c0[nt] + bv0), __expf(c1[nt] + bv1));
        float2 hi = make_float2(__expf(c2[nt] + bv0), __expf(c3[nt] + bv1));
        *reinterpret_cast<float2*>(g_X + r0 * TT + col)       = lo;
        *reinterpret_cast<float2*>(g_X + (r0 + 8) * TT + col) = hi;
    }
}

// ---------------------------------------------------------------------------
// Kernel 2 (Phase A): per-segment transport matrices via chained tf32 mma.
// Warp (b, g) computes P_g = M_{t1-1}...M_{t0}, M_t = diag(x_t) E, over its
// active steps [t0, t1) = [32g, min(32(g+1), len)); P_g = I if none.
// State P lives in C-fragment registers (m16n8k8 layout, M=32 pad, rows>=24
// stay zero). Per step: STS C -> smem (double buffer), LDS B-frags + x row
// scales, 18 mma (2m x 3n x 3k), row-scale by x. Exact power-of-2 renorm
// every 4 steps into Mexp.
// ---------------------------------------------------------------------------
__global__ __launch_bounds__(128) void seg_kernel(
    const float* __restrict__ trans,
    const int*   __restrict__ lengths)
{
    __shared__ float Psm[4][2][24 * 28];   // [warp][buf][row * 28 + col]
    __shared__ float xsm[4][SS * TT];      // [warp][step * 24 + tag]

    const int lane = threadIdx.x & 31;
    const int wid  = threadIdx.x >> 5;
    const int idx  = blockIdx.x * 4 + wid;   // 0..2047
    const int b = idx >> 4;
    const int g = idx & 15;

    const int gr = lane >> 2;   // groupID 0..7
    const int qt = lane & 3;    // threadID in group 0..3

    // Constant A-fragments of E (rows >= 24 are zero).
    unsigned A[2][3][4];
    #pragma unroll
    for (int m = 0; m < 2; ++m) {
        const int r0 = 16 * m + gr;
        const int r1 = r0 + 8;
        #pragma unroll
        for (int ks = 0; ks < 3; ++ks) {
            const int c0 = 8 * ks + qt;
            const int c1 = c0 + 4;
            A[m][ks][0] = (r0 < TT) ? f2tf32(__expf(trans[r0 * TT + c0])) : 0u;
            A[m][ks][1] = (r1 < TT) ? f2tf32(__expf(trans[r1 * TT + c0])) : 0u;
            A[m][ks][2] = (r0 < TT) ? f2tf32(__expf(trans[r0 * TT + c1])) : 0u;
            A[m][ks][3] = (r1 < TT) ? f2tf32(__expf(trans[r1 * TT + c1])) : 0u;
        }
    }

    // C-fragment state = identity (rows/cols >= 24 implicitly zero).
    float C[2][3][4];
    #pragma unroll
    for (int m = 0; m < 2; ++m) {
        const int r0 = 16 * m + gr;
        const int r1 = r0 + 8;
        #pragma unroll
        for (int nt = 0; nt < 3; ++nt) {
            const int col0 = 8 * nt + 2 * qt;
            const int col1 = col0 + 1;
            C[m][nt][0] = (r0 == col0) ? 1.f : 0.f;
            C[m][nt][1] = (r0 == col1) ? 1.f : 0.f;
            C[m][nt][2] = (r1 == col0 && r1 < TT) ? 1.f : 0.f;
            C[m][nt][3] = (r1 == col1 && r1 < TT) ? 1.f : 0.f;
        }
    }

    const int len = lengths[b];
    int steps = len - g * SS;
    steps = (steps < 0) ? 0 : ((steps > SS) ? SS : steps);

    // Stage this segment's emissions into smem: xsm[i*24 + tag], t = 32g + i.
    for (int i2 = lane; i2 < steps * TT; i2 += 32) {
        const int i = i2 / TT;
        const int tg = i2 - i * TT;
        xsm[wid][i2] = g_X[((size_t)b * LL + g * SS + i) * TT + tg];
    }
    __syncwarp();

    int Mexp = 0;

    for (int i = 0; i < steps; ++i) {
        float* Ps = &Psm[wid][i & 1][0];

        // STS current P (C-frags, rows < 24 only): 9 x STS.64
        #pragma unroll
        for (int nt = 0; nt < 3; ++nt) {
            const int col = 8 * nt + 2 * qt;
            *reinterpret_cast<float2*>(&Ps[gr * 28 + col]) =
                make_float2(C[0][nt][0], C[0][nt][1]);
            *reinterpret_cast<float2*>(&Ps[(gr + 8) * 28 + col]) =
                make_float2(C[0][nt][2], C[0][nt][3]);
            *reinterpret_cast<float2*>(&Ps[(16 + gr) * 28 + col]) =
                make_float2(C[1][nt][0], C[1][nt][1]);
        }
        __syncwarp();

        // B-fragments of P: b0 = P[k=qt+8ks][n=gr+8nt], b1 = P[k=qt+4+8ks][..]
        unsigned Bf[3][3][2];
        #pragma unroll
        for (int ks = 0; ks < 3; ++ks)
            #pragma unroll
            for (int nt = 0; nt < 3; ++nt) {
                Bf[ks][nt][0] = f2tf32(Ps[(qt + 8 * ks) * 28 + gr + 8 * nt]);
                Bf[ks][nt][1] = f2tf32(Ps[(qt + 4 + 8 * ks) * 28 + gr + 8 * nt]);
            }

        // emission scales for this lane's rows
        const float x0 = xsm[wid][i * TT + gr];
        const float x1 = xsm[wid][i * TT + gr + 8];
        const float x2 = xsm[wid][i * TT + 16 + gr];

        // Q = E * P
        float Q[2][3][4];
        #pragma unroll
        for (int m = 0; m < 2; ++m)
            #pragma unroll
            for (int nt = 0; nt < 3; ++nt) {
                Q[m][nt][0] = 0.f; Q[m][nt][1] = 0.f;
                Q[m][nt][2] = 0.f; Q[m][nt][3] = 0.f;
                #pragma unroll
                for (int ks = 0; ks < 3; ++ks)
                    MMA_TF32(Q[m][nt][0], Q[m][nt][1], Q[m][nt][2], Q[m][nt][3],
                             A[m][ks][0], A[m][ks][1], A[m][ks][2], A[m][ks][3],
                             Bf[ks][nt][0], Bf[ks][nt][1]);
            }

        // P' = diag(x) Q   (rows 24..31 remain zero)
        #pragma unroll
        for (int nt = 0; nt < 3; ++nt) {
            C[0][nt][0] = x0 * Q[0][nt][0];  C[0][nt][1] = x0 * Q[0][nt][1];
            C[0][nt][2] = x1 * Q[0][nt][2];  C[0][nt][3] = x1 * Q[0][nt][3];
            C[1][nt][0] = x2 * Q[1][nt][0];  C[1][nt][1] = x2 * Q[1][nt][1];
            C[1][nt][2] = 0.f;               C[1][nt][3] = 0.f;
        }

        // exact power-of-2 renorm every 4 steps
        if ((i & 3) == 3) {
            float mx = 0.f;
            #pragma unroll
            for (int m = 0; m < 2; ++m)
                #pragma unroll
                for (int nt = 0; nt < 3; ++nt) {
                    mx = fmaxf(mx, fmaxf(C[m][nt][0], C[m][nt][1]));
                    mx = fmaxf(mx, fmaxf(C[m][nt][2], C[m][nt][3]));
                }
            const unsigned mb =
                __reduce_max_sync(0xffffffffu, __float_as_uint(mx));
            const int e  = (int)(mb >> 23);
            const int en = (e == 0) ? 127 : e;
            const float nsc = __uint_as_float((unsigned)(254 - en) << 23);
            #pragma unroll
            for (int m = 0; m < 2; ++m)
                #pragma unroll
                for (int nt = 0; nt < 3; ++nt) {
                    C[m][nt][0] *= nsc; C[m][nt][1] *= nsc;
                    C[m][nt][2] *= nsc; C[m][nt][3] *= nsc;
                }
            Mexp += (en - 127);
        }
    }

    // Store P_g (rows < 24) and Mexp.
    float* Pg = g_P + (size_t)idx * 576;
    #pragma unroll
    for (int nt = 0; nt < 3; ++nt) {
        const int col = 8 * nt + 2 * qt;
        *reinterpret_cast<float2*>(&Pg[gr * TT + col]) =
            make_float2(C[0][nt][0], C[0][nt][1]);
        *reinterpret_cast<float2*>(&Pg[(gr + 8) * TT + col]) =
            make_float2(C[0][nt][2], C[0][nt][3]);
        *reinterpret_cast<float2*>(&Pg[(16 + gr) * TT + col]) =
            make_float2(C[1][nt][0], C[1][nt][1]);
    }
    if (lane == 0) g_M[idx] = Mexp;
}

// ---------------------------------------------------------------------------
// Kernel 3 (Phase B): fold the 16 segment matrices into the alpha vector.
// One warp per batch; 16 fully-unrolled steps; P rows prefetched into regs.
// ---------------------------------------------------------------------------
__global__ __launch_bounds__(32) void combine_kernel(
    const float* __restrict__ trans,
    float*       __restrict__ out)
{
    __shared__ __align__(16) float wbuf[2][32];

    const int lane = threadIdx.x;
    const int b = blockIdx.x;
    const int lanec = (lane < TT) ? lane : (TT - 1);

    const float u = (lane < TT) ? __expf(trans[TAG_STOP * TT + lane]) : 0.f;

    // sum of segment exponents
    int mg = (lane < SEG) ? g_M[b * SEG + lane] : 0;
    #pragma unroll
    for (int o = 8; o > 0; o >>= 1)
        mg += __shfl_xor_sync(0xffffffffu, mg, o);
    int Mtot = mg;

    float v = (lane == TAG_START) ? 1.f : 0.f;

    // prefetch P_0 row `lane`
    const float* Pb = g_P + (size_t)b * SEG * 576;
    float4 R[6];
    #pragma unroll
    for (int i = 0; i < 6; ++i)
        R[i] = *reinterpret_cast<const float4*>(Pb + lanec * TT + i * 4);

    #pragma unroll
    for (int g = 0; g < SEG; ++g) {
        const int p = g & 1;
        wbuf[p][lane] = v;

        // prefetch next segment's row
        const int gn = (g + 1 < SEG) ? (g + 1) : (SEG - 1);
        float4 Rn[6];
        #pragma unroll
        for (int i = 0; i < 6; ++i)
            Rn[i] = *reinterpret_cast<const float4*>(
                Pb + (size_t)gn * 576 + lanec * TT + i * 4);

        __syncwarp();

        const float4* vv = reinterpret_cast<const float4*>(&wbuf[p][0]);
        float a0 = 0.f, a1 = 0.f, a2 = 0.f, a3 = 0.f;
        #pragma unroll
        for (int i = 0; i < 6; ++i) {
            const float4 w4 = vv[i];
            a0 = fmaf(R[i].x, w4.x, a0);
            a1 = fmaf(R[i].y, w4.y, a1);
            a2 = fmaf(R[i].z, w4.z, a2);
            a3 = fmaf(R[i].w, w4.w, a3);
        }
        float vn = (a0 + a1) + (a2 + a3);
        vn = (lane < TT) ? vn : 0.f;

        // renorm each step (exact power-of-2)
        const unsigned mb = __reduce_max_sync(0xffffffffu, __float_as_uint(vn));
        const int e  = (int)(mb >> 23);
        const int en = (e == 0) ? 127 : e;
        const float nsc = __uint_as_float((unsigned)(254 - en) << 23);
        v = vn * nsc;
        Mtot += (en - 127);

        #pragma unroll
        for (int i = 0; i < 6; ++i) R[i] = Rn[i];
    }

    float term = v * u;
    #pragma unroll
    for (int o = 16; o > 0; o >>= 1)
        term += __shfl_xor_sync(0xffffffffu, term, o);

    if (lane == 0)
        out[b] = __logf(term) + (float)Mtot * 0.69314718055994531f;
}

extern "C" void kernel_launch(void* const* d_in, const int* in_sizes, int n_in,
                              void* d_out, int out_size)
{
    const float* feat   = (const float*)d_in[0];  // [128,512,512]
    const float* Wm     = (const float*)d_in[1];  // [24,512]
    const float* bias   = (const float*)d_in[2];  // [24]
    const float* trans  = (const float*)d_in[3];  // [24,24]
    const int*   lens   = (const int*)d_in[4];    // [128]
    float* out = (float*)d_out;                   // [128]

    emit_kernel<<<512, 256>>>(feat, Wm, bias);
    seg_kernel<<<512, 128>>>(trans, lens);
    combine_kernel<<<128, 32>>>(trans, out);
}

// round 10
// speedup vs baseline: 1.5805x; 1.1995x over previous
#include <cuda_runtime.h>
#include <cmath>

#define BB 128
#define LL 512
#define HH 512
#define TT 24
#define TAG_START 22
#define TAG_STOP  23
#define SEG 16
#define SS  32            // steps per segment = LL/SEG

// Scratch (device globals; no allocations).
__device__ float g_X[BB * LL * TT];          // exp(emissions)  6.3 MB
__device__ float g_P[BB * SEG * 576];        // segment transport matrices 4.7 MB
__device__ int   g_M[BB * SEG];              // segment exponent offsets

// m16n8k8 tf32 mma (used by seg_kernel)
#define MMA_TF32(c0,c1,c2,c3,a0,a1,a2,a3,b0,b1) \
  asm("mma.sync.aligned.m16n8k8.row.col.f32.tf32.tf32.f32 " \
      "{%0,%1,%2,%3},{%4,%5,%6,%7},{%8,%9},{%0,%1,%2,%3};" \
      : "+f"(c0),"+f"(c1),"+f"(c2),"+f"(c3) \
      : "r"(a0),"r"(a1),"r"(a2),"r"(a3),"r"(b0),"r"(b1))

// m16n8k16 bf16 mma (emit kernel)
#define MMA_BF16(c0,c1,c2,c3,a0,a1,a2,a3,b0,b1) \
  asm("mma.sync.aligned.m16n8k16.row.col.f32.bf16.bf16.f32 " \
      "{%0,%1,%2,%3},{%4,%5,%6,%7},{%8,%9},{%0,%1,%2,%3};" \
      : "+f"(c0),"+f"(c1),"+f"(c2),"+f"(c3) \
      : "r"(a0),"r"(a1),"r"(a2),"r"(a3),"r"(b0),"r"(b1))

__device__ __forceinline__ unsigned f2tf32(float v) {
    unsigned r;
    asm("cvt.rna.tf32.f32 %0, %1;" : "=r"(r) : "f"(v));
    return r;
}

// pack two floats into bf16x2: low half = lo (smaller k), high half = hi
__device__ __forceinline__ unsigned pk_bf16x2(float lo, float hi) {
    unsigned r;
    asm("cvt.rn.bf16x2.f32 %0, %1, %2;" : "=r"(r) : "f"(hi), "f"(lo));
    return r;
}

// ---------------------------------------------------------------------------
// Kernel 1: emission GEMM + exp via bf16 m16n8k16 tensor cores.
// Dense traffic: A staged through smem with coalesced LDG.128 (4 lines/instr)
// and conflict-free fragment LDS (bank = 4g+q, all distinct).  W stored
// transposed [n][k] in bf16, stride 520 (also conflict-free).
// CTA: 256 thr / 8 warps / 128 rows.  K pipelined in 8 chunks of 64.
// ---------------------------------------------------------------------------
#define SA 72     // A-tile row stride in bf16 units (64 used + 8 pad)
#define SK 520    // Wtn row stride in bf16 units (512 used + 8 pad)

__global__ void __launch_bounds__(256, 2) emit_kernel(
    const float* __restrict__ feat,
    const float* __restrict__ Wm,
    const float* __restrict__ bias)
{
    __shared__ unsigned short Wtn[TT * SK];    // 24.4 KB  bf16 W^T as [n][k]
    __shared__ unsigned short Asm[128 * SA];   // 18.0 KB  bf16 A chunk

    const int tid = threadIdx.x;

    // Stage Wtn[n][k] = bf16(Wm[n*512 + k])  (one-time, coalesced float4)
    for (int idx = tid; idx < TT * (HH / 4); idx += 256) {
        const int n  = idx >> 7;       // /128
        const int kq = idx & 127;      // float4 index within row
        const float4 wv = *reinterpret_cast<const float4*>(Wm + n * HH + kq * 4);
        uint2 p;
        p.x = pk_bf16x2(wv.x, wv.y);
        p.y = pk_bf16x2(wv.z, wv.w);
        *reinterpret_cast<uint2*>(&Wtn[n * SK + kq * 4]) = p;
    }

    // A staging mapping: thread -> (rowb = tid>>4, col4 = tid&15);
    // loads rows rowb + 16*i, 16B at col4*4 within the 64-col chunk.
    const int col4 = tid & 15;
    const int rowb = tid >> 4;
    const long rowCTA = (long)blockIdx.x * 128;
    const float* gbase = feat + (rowCTA + rowb) * HH + col4 * 4;

    // fragment identity
    const int warp = tid >> 5;
    const int lane = tid & 31;
    const int g = lane >> 2;
    const int q = lane & 3;
    const int r0 = warp * 16 + g;       // row within CTA

    float c0[3], c1[3], c2[3], c3[3];
    #pragma unroll
    for (int nt = 0; nt < 3; ++nt) { c0[nt]=0.f; c1[nt]=0.f; c2[nt]=0.f; c3[nt]=0.f; }

    // preload chunk 0
    float4 fr[8];
    #pragma unroll
    for (int i = 0; i < 8; ++i)
        fr[i] = *reinterpret_cast<const float4*>(gbase + (long)i * 16 * HH);

    for (int c = 0; c < 8; ++c) {
        __syncthreads();
        // store chunk to smem (bf16, swizzle-free padded layout)
        #pragma unroll
        for (int i = 0; i < 8; ++i) {
            uint2 p;
            p.x = pk_bf16x2(fr[i].x, fr[i].y);
            p.y = pk_bf16x2(fr[i].z, fr[i].w);
            *reinterpret_cast<uint2*>(&Asm[(rowb + 16 * i) * SA + col4 * 4]) = p;
        }
        __syncthreads();

        // prefetch next chunk under the mma work
        if (c < 7) {
            #pragma unroll
            for (int i = 0; i < 8; ++i)
                fr[i] = *reinterpret_cast<const float4*>(
                    gbase + (c + 1) * 64 + (long)i * 16 * HH);
        }

        // 4 k16 iterations over this 64-col chunk
        #pragma unroll
        for (int kk = 0; kk < 4; ++kk) {
            const int kl = kk * 16;
            const unsigned a0 = *reinterpret_cast<const unsigned*>(
                &Asm[r0 * SA + kl + 2 * q]);
            const unsigned a1 = *reinterpret_cast<const unsigned*>(
                &Asm[(r0 + 8) * SA + kl + 2 * q]);
            const unsigned a2 = *reinterpret_cast<const unsigned*>(
                &Asm[r0 * SA + kl + 8 + 2 * q]);
            const unsigned a3 = *reinterpret_cast<const unsigned*>(
                &Asm[(r0 + 8) * SA + kl + 8 + 2 * q]);

            const int kg = c * 64 + kl;
            #pragma unroll
            for (int nt = 0; nt < 3; ++nt) {
                const int n = 8 * nt + g;
                const unsigned b0 = *reinterpret_cast<const unsigned*>(
                    &Wtn[n * SK + kg + 2 * q]);
                const unsigned b1 = *reinterpret_cast<const unsigned*>(
                    &Wtn[n * SK + kg + 8 + 2 * q]);
                MMA_BF16(c0[nt], c1[nt], c2[nt], c3[nt],
                         a0, a1, a2, a3, b0, b1);
            }
        }
    }

    // epilogue: add bias, exp, store pairs (C layout: m16n8, same as tf32)
    const long rg = rowCTA + r0;
    #pragma unroll
    for (int nt = 0; nt < 3; ++nt) {
        const int col = nt * 8 + 2 * q;
        const float bv0 = __ldg(bias + col);
        const float bv1 = __ldg(bias + col + 1);
        float2 lo = make_float2(__expf(c0[nt] + bv0), __expf(c1[nt] + bv1));
        float2 hi = make_float2(__expf(c2[nt] + bv0), __expf(c3[nt] + bv1));
        *reinterpret_cast<float2*>(g_X + rg * TT + col)       = lo;
        *reinterpret_cast<float2*>(g_X + (rg + 8) * TT + col) = hi;
    }
}

// ---------------------------------------------------------------------------
// Kernel 2 (Phase A): per-segment transport matrices via chained tf32 mma.
// (unchanged from R9 — passing at rel_err 9.2e-7)
// ---------------------------------------------------------------------------
__global__ __launch_bounds__(128) void seg_kernel(
    const float* __restrict__ trans,
    const int*   __restrict__ lengths)
{
    __shared__ float Psm[4][2][24 * 28];
    __shared__ float xsm[4][SS * TT];

    const int lane = threadIdx.x & 31;
    const int wid  = threadIdx.x >> 5;
    const int idx  = blockIdx.x * 4 + wid;
    const int b = idx >> 4;
    const int g = idx & 15;

    const int gr = lane >> 2;
    const int qt = lane & 3;

    unsigned A[2][3][4];
    #pragma unroll
    for (int m = 0; m < 2; ++m) {
        const int r0 = 16 * m + gr;
        const int r1 = r0 + 8;
        #pragma unroll
        for (int ks = 0; ks < 3; ++ks) {
            const int c0 = 8 * ks + qt;
            const int c1 = c0 + 4;
            A[m][ks][0] = (r0 < TT) ? f2tf32(__expf(trans[r0 * TT + c0])) : 0u;
            A[m][ks][1] = (r1 < TT) ? f2tf32(__expf(trans[r1 * TT + c0])) : 0u;
            A[m][ks][2] = (r0 < TT) ? f2tf32(__expf(trans[r0 * TT + c1])) : 0u;
            A[m][ks][3] = (r1 < TT) ? f2tf32(__expf(trans[r1 * TT + c1])) : 0u;
        }
    }

    float C[2][3][4];
    #pragma unroll
    for (int m = 0; m < 2; ++m) {
        const int r0 = 16 * m + gr;
        const int r1 = r0 + 8;
        #pragma unroll
        for (int nt = 0; nt < 3; ++nt) {
            const int col0 = 8 * nt + 2 * qt;
            const int col1 = col0 + 1;
            C[m][nt][0] = (r0 == col0) ? 1.f : 0.f;
            C[m][nt][1] = (r0 == col1) ? 1.f : 0.f;
            C[m][nt][2] = (r1 == col0 && r1 < TT) ? 1.f : 0.f;
            C[m][nt][3] = (r1 == col1 && r1 < TT) ? 1.f : 0.f;
        }
    }

    const int len = lengths[b];
    int steps = len - g * SS;
    steps = (steps < 0) ? 0 : ((steps > SS) ? SS : steps);

    for (int i2 = lane; i2 < steps * TT; i2 += 32) {
        const int i = i2 / TT;
        const int tg = i2 - i * TT;
        xsm[wid][i2] = g_X[((size_t)b * LL + g * SS + i) * TT + tg];
    }
    __syncwarp();

    int Mexp = 0;

    for (int i = 0; i < steps; ++i) {
        float* Ps = &Psm[wid][i & 1][0];

        #pragma unroll
        for (int nt = 0; nt < 3; ++nt) {
            const int col = 8 * nt + 2 * qt;
            *reinterpret_cast<float2*>(&Ps[gr * 28 + col]) =
                make_float2(C[0][nt][0], C[0][nt][1]);
            *reinterpret_cast<float2*>(&Ps[(gr + 8) * 28 + col]) =
                make_float2(C[0][nt][2], C[0][nt][3]);
            *reinterpret_cast<float2*>(&Ps[(16 + gr) * 28 + col]) =
                make_float2(C[1][nt][0], C[1][nt][1]);
        }
        __syncwarp();

        unsigned Bf[3][3][2];
        #pragma unroll
        for (int ks = 0; ks < 3; ++ks)
            #pragma unroll
            for (int nt = 0; nt < 3; ++nt) {
                Bf[ks][nt][0] = f2tf32(Ps[(qt + 8 * ks) * 28 + gr + 8 * nt]);
                Bf[ks][nt][1] = f2tf32(Ps[(qt + 4 + 8 * ks) * 28 + gr + 8 * nt]);
            }

        const float x0 = xsm[wid][i * TT + gr];
        const float x1 = xsm[wid][i * TT + gr + 8];
        const float x2 = xsm[wid][i * TT + 16 + gr];

        float Q[2][3][4];
        #pragma unroll
        for (int m = 0; m < 2; ++m)
            #pragma unroll
            for (int nt = 0; nt < 3; ++nt) {
                Q[m][nt][0] = 0.f; Q[m][nt][1] = 0.f;
                Q[m][nt][2] = 0.f; Q[m][nt][3] = 0.f;
                #pragma unroll
                for (int ks = 0; ks < 3; ++ks)
                    MMA_TF32(Q[m][nt][0], Q[m][nt][1], Q[m][nt][2], Q[m][nt][3],
                             A[m][ks][0], A[m][ks][1], A[m][ks][2], A[m][ks][3],
                             Bf[ks][nt][0], Bf[ks][nt][1]);
            }

        #pragma unroll
        for (int nt = 0; nt < 3; ++nt) {
            C[0][nt][0] = x0 * Q[0][nt][0];  C[0][nt][1] = x0 * Q[0][nt][1];
            C[0][nt][2] = x1 * Q[0][nt][2];  C[0][nt][3] = x1 * Q[0][nt][3];
            C[1][nt][0] = x2 * Q[1][nt][0];  C[1][nt][1] = x2 * Q[1][nt][1];
            C[1][nt][2] = 0.f;               C[1][nt][3] = 0.f;
        }

        if ((i & 3) == 3) {
            float mx = 0.f;
            #pragma unroll
            for (int m = 0; m < 2; ++m)
                #pragma unroll
                for (int nt = 0; nt < 3; ++nt) {
                    mx = fmaxf(mx, fmaxf(C[m][nt][0], C[m][nt][1]));
                    mx = fmaxf(mx, fmaxf(C[m][nt][2], C[m][nt][3]));
                }
            const unsigned mb =
                __reduce_max_sync(0xffffffffu, __float_as_uint(mx));
            const int e  = (int)(mb >> 23);
            const int en = (e == 0) ? 127 : e;
            const float nsc = __uint_as_float((unsigned)(254 - en) << 23);
            #pragma unroll
            for (int m = 0; m < 2; ++m)
                #pragma unroll
                for (int nt = 0; nt < 3; ++nt) {
                    C[m][nt][0] *= nsc; C[m][nt][1] *= nsc;
                    C[m][nt][2] *= nsc; C[m][nt][3] *= nsc;
                }
            Mexp += (en - 127);
        }
    }

    float* Pg = g_P + (size_t)idx * 576;
    #pragma unroll
    for (int nt = 0; nt < 3; ++nt) {
        const int col = 8 * nt + 2 * qt;
        *reinterpret_cast<float2*>(&Pg[gr * TT + col]) =
            make_float2(C[0][nt][0], C[0][nt][1]);
        *reinterpret_cast<float2*>(&Pg[(gr + 8) * TT + col]) =
            make_float2(C[0][nt][2], C[0][nt][3]);
        *reinterpret_cast<float2*>(&Pg[(16 + gr) * TT + col]) =
            make_float2(C[1][nt][0], C[1][nt][1]);
    }
    if (lane == 0) g_M[idx] = Mexp;
}

// ---------------------------------------------------------------------------
// Kernel 3 (Phase B): fold the 16 segment matrices into the alpha vector.
// (unchanged from R9)
// ---------------------------------------------------------------------------
__global__ __launch_bounds__(32) void combine_kernel(
    const float* __restrict__ trans,
    float*       __restrict__ out)
{
    __shared__ __align__(16) float wbuf[2][32];

    const int lane = threadIdx.x;
    const int b = blockIdx.x;
    const int lanec = (lane < TT) ? lane : (TT - 1);

    const float u = (lane < TT) ? __expf(trans[TAG_STOP * TT + lane]) : 0.f;

    int mg = (lane < SEG) ? g_M[b * SEG + lane] : 0;
    #pragma unroll
    for (int o = 8; o > 0; o >>= 1)
        mg += __shfl_xor_sync(0xffffffffu, mg, o);
    int Mtot = mg;

    float v = (lane == TAG_START) ? 1.f : 0.f;

    const float* Pb = g_P + (size_t)b * SEG * 576;
    float4 R[6];
    #pragma unroll
    for (int i = 0; i < 6; ++i)
        R[i] = *reinterpret_cast<const float4*>(Pb + lanec * TT + i * 4);

    #pragma unroll
    for (int g = 0; g < SEG; ++g) {
        const int p = g & 1;
        wbuf[p][lane] = v;

        const int gn = (g + 1 < SEG) ? (g + 1) : (SEG - 1);
        float4 Rn[6];
        #pragma unroll
        for (int i = 0; i < 6; ++i)
            Rn[i] = *reinterpret_cast<const float4*>(
                Pb + (size_t)gn * 576 + lanec * TT + i * 4);

        __syncwarp();

        const float4* vv = reinterpret_cast<const float4*>(&wbuf[p][0]);
        float a0 = 0.f, a1 = 0.f, a2 = 0.f, a3 = 0.f;
        #pragma unroll
        for (int i = 0; i < 6; ++i) {
            const float4 w4 = vv[i];
            a0 = fmaf(R[i].x, w4.x, a0);
            a1 = fmaf(R[i].y, w4.y, a1);
            a2 = fmaf(R[i].z, w4.z, a2);
            a3 = fmaf(R[i].w, w4.w, a3);
        }
        float vn = (a0 + a1) + (a2 + a3);
        vn = (lane < TT) ? vn : 0.f;

        const unsigned mb = __reduce_max_sync(0xffffffffu, __float_as_uint(vn));
        const int e  = (int)(mb >> 23);
        const int en = (e == 0) ? 127 : e;
        const float nsc = __uint_as_float((unsigned)(254 - en) << 23);
        v = vn * nsc;
        Mtot += (en - 127);

        #pragma unroll
        for (int i = 0; i < 6; ++i) R[i] = Rn[i];
    }

    float term = v * u;
    #pragma unroll
    for (int o = 16; o > 0; o >>= 1)
        term += __shfl_xor_sync(0xffffffffu, term, o);

    if (lane == 0)
        out[b] = __logf(term) + (float)Mtot * 0.69314718055994531f;
}

extern "C" void kernel_launch(void* const* d_in, const int* in_sizes, int n_in,
                              void* d_out, int out_size)
{
    const float* feat   = (const float*)d_in[0];  // [128,512,512]
    const float* Wm     = (const float*)d_in[1];  // [24,512]
    const float* bias   = (const float*)d_in[2];  // [24]
    const float* trans  = (const float*)d_in[3];  // [24,24]
    const int*   lens   = (const int*)d_in[4];    // [128]
    float* out = (float*)d_out;                   // [128]

    emit_kernel<<<512, 256>>>(feat, Wm, bias);
    seg_kernel<<<512, 128>>>(trans, lens);
    combine_kernel<<<128, 32>>>(trans, out);
}